// round 3
// baseline (speedup 1.0000x reference)
#include <cuda_runtime.h>

#define N 8192
#define BB 2
#define CH 64
#define KNB 16
#define FULLMASK 0xffffffffu
typedef unsigned long long ull;

// ---------------- scratch (static device globals; no allocation) ----------------
__device__ float g_q1[BB*N*CH];
__device__ float g_q2[BB*N*CH];
__device__ float g_r1[BB*N*CH];
__device__ float g_r2[BB*N*CH];
__device__ float g_f1[BB*N*CH];
__device__ float g_f2[BB*N*CH];
__device__ int   g_i12[BB*N*KNB];
__device__ int   g_i21[BB*N*KNB];

__device__ __forceinline__ float leaky(float x) { return fmaxf(x, 0.1f * x); }

// ---------------- packed f32x2 helpers ----------------
__device__ __forceinline__ ull ffma2(ull a, ull b, ull c) {
    ull d; asm("fma.rn.f32x2 %0, %1, %2, %3;" : "=l"(d) : "l"(a), "l"(b), "l"(c)); return d;
}
__device__ __forceinline__ ull pk2(float x, float y) {
    ull r; asm("mov.b64 %0, {%1, %2};" : "=l"(r) : "f"(x), "f"(y)); return r;
}
__device__ __forceinline__ ull dup2(float x) {
    ull r; asm("mov.b64 %0, {%1, %1};" : "=l"(r) : "f"(x)); return r;
}
__device__ __forceinline__ void unpk2(float& lo, float& hi, ull v) {
    asm("mov.b64 {%0, %1}, %2;" : "=f"(lo), "=f"(hi) : "l"(v));
}
__device__ __forceinline__ ull lky2(ull v) {
    float a, b; unpk2(a, b, v);
    return pk2(fmaxf(a, 0.1f * a), fmaxf(b, 0.1f * b));
}

// ================= fused KNN (z=0,1) + 4-way transform (z=2) =================
#define TILE 2048
__device__ __forceinline__ void knn_insert(float& bd, int& bi, float dd, int jj, int lane) {
    float up = __shfl_up_sync(FULLMASK, bd, 1);
    int  upi = __shfl_up_sync(FULLMASK, bi, 1);
    if (lane == 0) up = -3.0e38f;
    if (bd > dd) {
        bool tk = up > dd;
        bd = tk ? up : dd;
        bi = tk ? upi : jj;
    }
}

__global__ __launch_bounds__(512) void knn_transform_kernel(
    const float* __restrict__ pc1, const float* __restrict__ pc2,
    int* __restrict__ i12, int* __restrict__ i21,
    const float* __restrict__ f1g, const float* __restrict__ f2g,
    const float* __restrict__ w11, const float* __restrict__ b11,
    const float* __restrict__ w22, const float* __restrict__ b22,
    float* __restrict__ q1o, float* __restrict__ q2o,
    float* __restrict__ r1o, float* __restrict__ r2o)
{
    extern __shared__ char smraw[];
    const int tid = threadIdx.x;

    if (blockIdx.z == 2) {
        // ---- 4-way feature transform: 16 points per block ----
        ull* s_wp  = (ull*)smraw;       // 4096: [c][m] = (w11[m][c], w22[m][c])
        ull* s_f12 = s_wp + 4096;       // 1024: [c][np] = (f1, f2)
        ull* s_f21 = s_f12 + 1024;      // 1024: [c][np] = (f2, f1)
        const int b = blockIdx.y, n0 = blockIdx.x * 16;
        for (int i = tid; i < 4096; i += 512) {
            int m = i >> 6, c = i & 63;
            s_wp[c * 64 + m] = pk2(w11[i], w22[i]);
        }
        for (int i = tid; i < 1024; i += 512) {
            int c = i >> 4, np = i & 15;
            float a = f1g[(b * 64 + c) * N + n0 + np];
            float d = f2g[(b * 64 + c) * N + n0 + np];
            s_f12[i] = pk2(a, d);
            s_f21[i] = pk2(d, a);
        }
        __syncthreads();
        const int m = tid & 63, grp = tid >> 6;  // grp 0..7, 2 points each
        ull bq = pk2(b11[m], b22[m]);
        ull a0 = bq, a1 = bq, r0 = bq, r1v = bq;
        const int np = grp * 2;
        #pragma unroll 8
        for (int c = 0; c < 64; c++) {
            ull wv = s_wp[c * 64 + m];
            a0  = ffma2(s_f12[c * 16 + np],     wv, a0);
            a1  = ffma2(s_f12[c * 16 + np + 1], wv, a1);
            r0  = ffma2(s_f21[c * 16 + np],     wv, r0);
            r1v = ffma2(s_f21[c * 16 + np + 1], wv, r1v);
        }
        float v1, v2;
        int q = (b * N + n0 + np) * 64 + m;
        unpk2(v1, v2, a0);  q1o[q] = v1;      q2o[q] = v2;
        unpk2(v1, v2, a1);  q1o[q + 64] = v1; q2o[q + 64] = v2;
        unpk2(v1, v2, r0);  r1o[q] = v1;      r2o[q] = v2;
        unpk2(v1, v2, r1v); r1o[q + 64] = v1; r2o[q + 64] = v2;
        return;
    }

    // ---- KNN: metric m = |p|^2 - 2 p.q (same ordering as squared distance) ----
    ulonglong2* s_pa = (ulonglong2*)smraw;   // 1024: (x-pair, y-pair)
    ulonglong2* s_pb = s_pa + 1024;          // 1024: (z-pair, |p|^2-pair)
    const int dir = blockIdx.z;
    const float* q  = dir ? pc2 : pc1;
    const float* db = dir ? pc1 : pc2;
    int* oi = dir ? i21 : i12;
    const int b = blockIdx.y;
    const int warp = tid >> 5, lane = tid & 31;
    const int n = blockIdx.x * 16 + warp;
    const float* qb = q + b * 3 * N;
    const ull m2qx = dup2(-2.0f * qb[n]);
    const ull m2qy = dup2(-2.0f * qb[N + n]);
    const ull m2qz = dup2(-2.0f * qb[2 * N + n]);
    const float* dbb = db + b * 3 * N;

    float bd = 3.0e38f;
    int bi = 0;
    float tau = 3.0e38f;

    for (int t = 0; t < N; t += TILE) {
        __syncthreads();
        const float2* gx = (const float2*)(dbb + t);
        const float2* gy = (const float2*)(dbb + N + t);
        const float2* gz = (const float2*)(dbb + 2 * N + t);
        for (int i = tid; i < TILE / 2; i += 512) {
            float2 x = gx[i], y = gy[i], z = gz[i];
            float w0 = x.x * x.x + y.x * y.x + z.x * z.x;
            float w1 = x.y * x.y + y.y * y.y + z.y * z.y;
            ulonglong2 A, B;
            A.x = *(const ull*)&x; A.y = *(const ull*)&y;
            B.x = *(const ull*)&z; B.y = pk2(w0, w1);
            s_pa[i] = A; s_pb[i] = B;
        }
        __syncthreads();
        for (int p = 0; p < TILE / 2; p += 32) {
            ulonglong2 A = s_pa[p + lane];
            ulonglong2 B = s_pb[p + lane];
            ull d2 = ffma2(A.x, m2qx, B.y);
            d2 = ffma2(A.y, m2qy, d2);
            d2 = ffma2(B.x, m2qz, d2);
            float d0, d1; unpk2(d0, d1, d2);
            unsigned m0 = __ballot_sync(FULLMASK, d0 < tau);
            unsigned m1 = __ballot_sync(FULLMASK, d1 < tau);
            if (m0 | m1) {
                const int base = t + 2 * p;
                while (m0) {
                    int src = __ffs(m0) - 1; m0 &= m0 - 1;
                    float dd = __shfl_sync(FULLMASK, d0, src);
                    knn_insert(bd, bi, dd, base + 2 * src, lane);
                }
                while (m1) {
                    int src = __ffs(m1) - 1; m1 &= m1 - 1;
                    float dd = __shfl_sync(FULLMASK, d1, src);
                    knn_insert(bd, bi, dd, base + 2 * src + 1, lane);
                }
                tau = __shfl_sync(FULLMASK, bd, 15);
            }
        }
    }
    if (lane < 16) oi[((b * N) + n) * 16 + lane] = bi;
}

// ================= fused cross (+ optional final-linear epilogue) =================
// smem float offsets
#define OW1 0
#define OW2 4096
#define OW3 8192
#define OPWT 12288
#define OPB  12480
#define OB1  12544
#define OB2  12608
#define OB3  12672
#define OHP  12736                 // ull region: 8 warps * 512 = 4096 ull
#define OST  (12736 + 4096*2)      // float offset of stash: 8 warps * 256 ull
#define SMEM_FLOATS (12736 + 4096*2 + 2048*2)

template <int NL, int EPI>
__global__ __launch_bounds__(256) void cross_kernel(
    const int* __restrict__ iA, const int* __restrict__ iB,
    const float* __restrict__ xA, const float* __restrict__ xB,
    const float* __restrict__ p1A, const float* __restrict__ p2A,
    const float* __restrict__ p1B, const float* __restrict__ p2B,
    const float* __restrict__ posw, const float* __restrict__ posb,
    const float* __restrict__ w1, const float* __restrict__ b1,
    const float* __restrict__ w2, const float* __restrict__ b2,
    const float* __restrict__ w3A, const float* __restrict__ b3A,
    const float* __restrict__ w3B, const float* __restrict__ b3B,
    float* __restrict__ obnA, float* __restrict__ obnB,
    float* __restrict__ ocnA, float* __restrict__ ocnB)
{
    extern __shared__ float sm[];
    float* s_w1  = sm + OW1;
    float* s_w2  = sm + OW2;
    float* s_w3  = sm + OW3;
    float* s_pwt = sm + OPWT;
    float* s_pb  = sm + OPB;
    float* s_b1  = sm + OB1;
    float* s_b2  = sm + OB2;
    float* s_b3  = sm + OB3;
    ull*   s_hp  = (ull*)(sm + OHP);
    ull*   s_st  = (ull*)(sm + OST);

    const int dir = blockIdx.y;
    const int* idx = dir ? iB : iA;
    const float* xyz1 = dir ? xB : xA;
    const float* xyz2 = dir ? xA : xB;
    const float* p1 = dir ? p1B : p1A;
    const float* p2 = dir ? p2B : p2A;
    const float* w3 = dir ? w3B : w3A;
    const float* b3 = dir ? b3B : b3A;
    float* obn = dir ? obnB : obnA;
    float* ocn = dir ? ocnB : ocnA;

    const int tid = threadIdx.x;
    for (int i = tid; i < 4096; i += 256) {
        int jb = i >> 8, c = (i >> 2) & 63, u = i & 3;
        s_w1[i] = w1[c * 64 + jb * 4 + u];
        if (NL == 2) s_w2[i] = w2[c * 64 + jb * 4 + u];
        if (EPI)     s_w3[i] = w3[c * 64 + jb * 4 + u];
    }
    if (tid < 192) s_pwt[tid] = posw[(tid & 63) * 3 + (tid >> 6)];
    if (tid < 64) {
        s_pb[tid] = posb[tid];
        s_b1[tid] = b1[tid];
        if (NL == 2) s_b2[tid] = b2[tid];
        if (EPI)     s_b3[tid] = b3[tid];
    }
    __syncthreads();

    const int warp = tid >> 5, lane = tid & 31;
    ull* shp = s_hp + warp * 512;
    ull* sst = s_st + warp * 256;
    const int wq0 = (blockIdx.x * 8 + warp) * 8;

    const float pw0a = s_pwt[lane],      pw1a = s_pwt[64 + lane],  pw2a = s_pwt[128 + lane];
    const float pw0b = s_pwt[lane + 32], pw1b = s_pwt[96 + lane],  pw2b = s_pwt[160 + lane];
    const float pba = s_pb[lane], pbb = s_pb[lane + 32];
    const ull bd1a = dup2(s_b1[lane]), bd1b = dup2(s_b1[lane + 32]);
    const ull bd2a = (NL == 2) ? dup2(s_b2[lane]) : 0ull;
    const ull bd2b = (NL == 2) ? dup2(s_b2[lane + 32]) : 0ull;

    float pma = 0.f, pmb = 0.f;

    for (int qi = 0; qi < 8; qi++) {
        const int q = wq0 + qi;
        const int b = q >> 13, n = q & (N - 1);
        const int myidx = idx[q * 16 + (lane & 15)];
        const float p1a = p1[q * 64 + lane];
        const float p1b = p1[q * 64 + 32 + lane];
        const float* x1b = xyz1 + b * 3 * N;
        const float qx = x1b[n], qy = x1b[N + n], qz = x1b[2 * N + n];
        const float* x2b = xyz2 + b * 3 * N;
        const float nx = x2b[myidx], ny = x2b[N + myidx], nz = x2b[2 * N + myidx];

        float pva = 0.f, pvb = 0.f;
        #pragma unroll
        for (int k = 0; k < 16; k++) {
            int j = __shfl_sync(FULLMASK, myidx, k);
            float dx = __shfl_sync(FULLMASK, nx, k) - qx;
            float dy = __shfl_sync(FULLMASK, ny, k) - qy;
            float dz = __shfl_sync(FULLMASK, nz, k) - qz;
            const float* p2r = p2 + ((size_t)((b << 13) + j)) * 64;
            float ga = p2r[lane], gb = p2r[lane + 32];
            float pa = pba + dx * pw0a + dy * pw1a + dz * pw2a;
            float pb = pbb + dx * pw0b + dy * pw1b + dz * pw2b;
            float ha = leaky(ga + p1a + pa);
            float hb = leaky(gb + p1b + pb);
            if (k & 1) {
                shp[(k >> 1) * 64 + lane]      = pk2(pva, ha);
                shp[(k >> 1) * 64 + lane + 32] = pk2(pvb, hb);
            } else { pva = ha; pvb = hb; }
        }
        __syncwarp();

        ull ya[8], yb[8];
        #pragma unroll
        for (int k2 = 0; k2 < 8; k2++) { ya[k2] = bd1a; yb[k2] = bd1b; }
        #pragma unroll
        for (int jb = 0; jb < 16; jb++) {
            float4 wa = *(const float4*)(s_w1 + (jb * 64 + lane) * 4);
            float4 wb = *(const float4*)(s_w1 + (jb * 64 + lane + 32) * 4);
            ull wax = dup2(wa.x), way = dup2(wa.y), waz = dup2(wa.z), waw = dup2(wa.w);
            ull wbx = dup2(wb.x), wby = dup2(wb.y), wbz = dup2(wb.z), wbw = dup2(wb.w);
            #pragma unroll
            for (int k2 = 0; k2 < 8; k2++) {
                ulonglong2 h01 = *(const ulonglong2*)(shp + k2 * 64 + jb * 4);
                ulonglong2 h23 = *(const ulonglong2*)(shp + k2 * 64 + jb * 4 + 2);
                ya[k2] = ffma2(h01.x, wax, ya[k2]);
                yb[k2] = ffma2(h01.x, wbx, yb[k2]);
                ya[k2] = ffma2(h01.y, way, ya[k2]);
                yb[k2] = ffma2(h01.y, wby, yb[k2]);
                ya[k2] = ffma2(h23.x, waz, ya[k2]);
                yb[k2] = ffma2(h23.x, wbz, yb[k2]);
                ya[k2] = ffma2(h23.y, waw, ya[k2]);
                yb[k2] = ffma2(h23.y, wbw, yb[k2]);
            }
        }

        if (NL == 2) {
            __syncwarp();
            #pragma unroll
            for (int k2 = 0; k2 < 8; k2++) {
                shp[k2 * 64 + lane]      = lky2(ya[k2]);
                shp[k2 * 64 + lane + 32] = lky2(yb[k2]);
            }
            __syncwarp();
            #pragma unroll
            for (int k2 = 0; k2 < 8; k2++) { ya[k2] = bd2a; yb[k2] = bd2b; }
            #pragma unroll
            for (int jb = 0; jb < 16; jb++) {
                float4 wa = *(const float4*)(s_w2 + (jb * 64 + lane) * 4);
                float4 wb = *(const float4*)(s_w2 + (jb * 64 + lane + 32) * 4);
                ull wax = dup2(wa.x), way = dup2(wa.y), waz = dup2(wa.z), waw = dup2(wa.w);
                ull wbx = dup2(wb.x), wby = dup2(wb.y), wbz = dup2(wb.z), wbw = dup2(wb.w);
                #pragma unroll
                for (int k2 = 0; k2 < 8; k2++) {
                    ulonglong2 h01 = *(const ulonglong2*)(shp + k2 * 64 + jb * 4);
                    ulonglong2 h23 = *(const ulonglong2*)(shp + k2 * 64 + jb * 4 + 2);
                    ya[k2] = ffma2(h01.x, wax, ya[k2]);
                    yb[k2] = ffma2(h01.x, wbx, yb[k2]);
                    ya[k2] = ffma2(h01.y, way, ya[k2]);
                    yb[k2] = ffma2(h01.y, wby, yb[k2]);
                    ya[k2] = ffma2(h23.x, waz, ya[k2]);
                    yb[k2] = ffma2(h23.x, wbz, yb[k2]);
                    ya[k2] = ffma2(h23.y, waw, ya[k2]);
                    yb[k2] = ffma2(h23.y, wbw, yb[k2]);
                }
            }
        }

        float ma = -3.0e38f, mb = -3.0e38f;
        #pragma unroll
        for (int k2 = 0; k2 < 8; k2++) {
            float u, v;
            unpk2(u, v, ya[k2]); ma = fmaxf(ma, fmaxf(u, v));
            unpk2(u, v, yb[k2]); mb = fmaxf(mb, fmaxf(u, v));
        }
        ma = leaky(ma); mb = leaky(mb);

        if (EPI) {
            if (qi & 1) {
                sst[(qi >> 1) * 64 + lane]      = pk2(pma, ma);
                sst[(qi >> 1) * 64 + 32 + lane] = pk2(pmb, mb);
            } else { pma = ma; pmb = mb; }
        } else {
            // transposed direct write (cross3)
            ocn[((b * 64) + lane) * N + n] = ma;
            ocn[((b * 64) + lane + 32) * N + n] = mb;
        }
        __syncwarp();
    }

    if (EPI) {
        __syncwarp();
        ull za[4], zb[4];
        const ull bd3a = dup2(s_b3[lane]), bd3b = dup2(s_b3[lane + 32]);
        #pragma unroll
        for (int q2 = 0; q2 < 4; q2++) { za[q2] = bd3a; zb[q2] = bd3b; }
        #pragma unroll
        for (int jb = 0; jb < 16; jb++) {
            float4 wa = *(const float4*)(s_w3 + (jb * 64 + lane) * 4);
            float4 wb = *(const float4*)(s_w3 + (jb * 64 + lane + 32) * 4);
            ull wax = dup2(wa.x), way = dup2(wa.y), waz = dup2(wa.z), waw = dup2(wa.w);
            ull wbx = dup2(wb.x), wby = dup2(wb.y), wbz = dup2(wb.z), wbw = dup2(wb.w);
            #pragma unroll
            for (int q2 = 0; q2 < 4; q2++) {
                ulonglong2 h01 = *(const ulonglong2*)(sst + q2 * 64 + jb * 4);
                ulonglong2 h23 = *(const ulonglong2*)(sst + q2 * 64 + jb * 4 + 2);
                za[q2] = ffma2(h01.x, wax, za[q2]);
                zb[q2] = ffma2(h01.x, wbx, zb[q2]);
                za[q2] = ffma2(h01.y, way, za[q2]);
                zb[q2] = ffma2(h01.y, wby, zb[q2]);
                za[q2] = ffma2(h23.x, waz, za[q2]);
                zb[q2] = ffma2(h23.x, wbz, zb[q2]);
                za[q2] = ffma2(h23.y, waw, za[q2]);
                zb[q2] = ffma2(h23.y, wbw, zb[q2]);
            }
        }
        #pragma unroll
        for (int q2 = 0; q2 < 4; q2++) {
            const int q = wq0 + 2 * q2;
            const int b = q >> 13, n = q & (N - 1);
            float lo, hi;
            unpk2(lo, hi, za[q2]);
            obn[q * 64 + lane] = lo;
            obn[(q + 1) * 64 + lane] = hi;
            *(float2*)&ocn[((b * 64) + lane) * N + n] = make_float2(lo, hi);
            unpk2(lo, hi, zb[q2]);
            obn[q * 64 + 32 + lane] = lo;
            obn[(q + 1) * 64 + 32 + lane] = hi;
            *(float2*)&ocn[((b * 64) + lane + 32) * N + n] = make_float2(lo, hi);
        }
    }
}

// ---------------- launch ----------------
extern "C" void kernel_launch(void* const* d_in, const int* in_sizes, int n_in,
                              void* d_out, int out_size)
{
    const float* pc1     = (const float*)d_in[0];
    const float* pc2     = (const float*)d_in[1];
    const float* feat1   = (const float*)d_in[2];
    const float* feat2   = (const float*)d_in[3];
    const float* t11_w   = (const float*)d_in[4];
    const float* t11_b   = (const float*)d_in[5];
    const float* t22_w   = (const float*)d_in[6];
    const float* t22_b   = (const float*)d_in[7];
    const float* pos1_w  = (const float*)d_in[8];
    const float* pos1_b  = (const float*)d_in[9];
    const float* mlp1_w1 = (const float*)d_in[10];
    const float* mlp1_b1 = (const float*)d_in[11];
    const float* mlp1_w2 = (const float*)d_in[12];
    const float* mlp1_b2 = (const float*)d_in[13];
    const float* t1_w    = (const float*)d_in[14];
    const float* t1_b    = (const float*)d_in[15];
    const float* t2_w    = (const float*)d_in[16];
    const float* t2_b    = (const float*)d_in[17];
    const float* pos2_w  = (const float*)d_in[18];
    const float* pos2_b  = (const float*)d_in[19];
    const float* mlp2_w1 = (const float*)d_in[20];
    const float* mlp2_b1 = (const float*)d_in[21];
    float* out = (float*)d_out;

    float *q1, *q2, *r1, *r2, *f1, *f2;
    int *i12, *i21;
    cudaGetSymbolAddress((void**)&q1, g_q1);
    cudaGetSymbolAddress((void**)&q2, g_q2);
    cudaGetSymbolAddress((void**)&r1, g_r1);
    cudaGetSymbolAddress((void**)&r2, g_r2);
    cudaGetSymbolAddress((void**)&f1, g_f1);
    cudaGetSymbolAddress((void**)&f2, g_f2);
    cudaGetSymbolAddress((void**)&i12, g_i12);
    cudaGetSymbolAddress((void**)&i21, g_i21);

    // fused KNN (z=0,1) + transforms (z=2), one launch
    const size_t smem_kt = 49152;
    cudaFuncSetAttribute(knn_transform_kernel, cudaFuncAttributeMaxDynamicSharedMemorySize, (int)smem_kt);
    knn_transform_kernel<<<dim3(N / 16, BB, 3), 512, smem_kt>>>(
        pc1, pc2, i12, i21,
        feat1, feat2, t11_w, t11_b, t22_w, t22_b,
        q1, q2, r1, r2);

    const size_t smem = (size_t)SMEM_FLOATS * sizeof(float);
    cudaFuncSetAttribute(cross_kernel<2,1>, cudaFuncAttributeMaxDynamicSharedMemorySize, (int)smem);
    cudaFuncSetAttribute(cross_kernel<1,0>, cudaFuncAttributeMaxDynamicSharedMemorySize, (int)smem);

    // cross 1 & 2 fused (grid.y = direction) with final-linear epilogue:
    // writes f1/f2 ([B,N,64]) and output regions 0/1 ([B,64,N])
    cross_kernel<2,1><<<dim3(BB * N / 64, 2), 256, smem>>>(
        i12, i21, pc1, pc2,
        q1, q2, r1, r2,
        pos1_w, pos1_b, mlp1_w1, mlp1_b1, mlp1_w2, mlp1_b2,
        t1_w, t1_b, t2_w, t2_b,
        f1, f2, out, out + (size_t)BB * 64 * N);

    // cross 3 (1 mlp layer), transposed direct write to output region 2
    cross_kernel<1,0><<<dim3(BB * N / 64, 1), 256, smem>>>(
        i12, i12, pc1, pc2,
        f1, f2, f1, f2,
        pos2_w, pos2_b, mlp2_w1, mlp2_b1, mlp2_w1, mlp2_b1,
        mlp2_w1, mlp2_b1, mlp2_w1, mlp2_b1,
        out + (size_t)2 * BB * 64 * N, out + (size_t)2 * BB * 64 * N,
        out + (size_t)2 * BB * 64 * N, out + (size_t)2 * BB * 64 * N);
}

// round 4
// speedup vs baseline: 1.1340x; 1.1340x over previous
#include <cuda_runtime.h>

#define N 8192
#define BB 2
#define CH 64
#define KNB 16
#define FULLMASK 0xffffffffu
typedef unsigned long long ull;

// ---------------- scratch (static device globals; no allocation) ----------------
__device__ float g_q1[BB*N*CH];
__device__ float g_q2[BB*N*CH];
__device__ float g_r1[BB*N*CH];
__device__ float g_r2[BB*N*CH];
__device__ float g_f1[BB*N*CH];
__device__ float g_f2[BB*N*CH];
__device__ int   g_i12[BB*N*KNB];
__device__ int   g_i21[BB*N*KNB];

__device__ __forceinline__ float leaky(float x) { return fmaxf(x, 0.1f * x); }

// ---------------- packed f32x2 helpers ----------------
__device__ __forceinline__ ull ffma2(ull a, ull b, ull c) {
    ull d; asm("fma.rn.f32x2 %0, %1, %2, %3;" : "=l"(d) : "l"(a), "l"(b), "l"(c)); return d;
}
__device__ __forceinline__ ull pk2(float x, float y) {
    ull r; asm("mov.b64 %0, {%1, %2};" : "=l"(r) : "f"(x), "f"(y)); return r;
}
__device__ __forceinline__ ull dup2(float x) {
    ull r; asm("mov.b64 %0, {%1, %1};" : "=l"(r) : "f"(x)); return r;
}
__device__ __forceinline__ void unpk2(float& lo, float& hi, ull v) {
    asm("mov.b64 {%0, %1}, %2;" : "=f"(lo), "=f"(hi) : "l"(v));
}
__device__ __forceinline__ ull lky2(ull v) {
    float a, b; unpk2(a, b, v);
    return pk2(fmaxf(a, 0.1f * a), fmaxf(b, 0.1f * b));
}

// ================= fused KNN (z=0,1; 2 queries/warp) + 4-way transform (z=2) =================
#define TILE 4096   // points per smem tile (2048 pairs * 32B = 64KB)

__global__ __launch_bounds__(512) void knn_transform_kernel(
    const float* __restrict__ pc1, const float* __restrict__ pc2,
    int* __restrict__ i12, int* __restrict__ i21,
    const float* __restrict__ f1g, const float* __restrict__ f2g,
    const float* __restrict__ w11, const float* __restrict__ b11,
    const float* __restrict__ w22, const float* __restrict__ b22,
    float* __restrict__ q1o, float* __restrict__ q2o,
    float* __restrict__ r1o, float* __restrict__ r2o)
{
    extern __shared__ char smraw[];
    const int tid = threadIdx.x;

    if (blockIdx.z == 2) {
        // ---- 4-way feature transform: 16 points per block ----
        ull* s_wp  = (ull*)smraw;       // 4096: [c][m] = (w11[m][c], w22[m][c])
        ull* s_f12 = s_wp + 4096;       // 1024: [c][np] = (f1, f2)
        ull* s_f21 = s_f12 + 1024;      // 1024: [c][np] = (f2, f1)
        const int b = blockIdx.y, n0 = blockIdx.x * 16;
        for (int i = tid; i < 4096; i += 512) {
            int m = i >> 6, c = i & 63;
            s_wp[c * 64 + m] = pk2(w11[i], w22[i]);
        }
        for (int i = tid; i < 1024; i += 512) {
            int c = i >> 4, np = i & 15;
            float a = f1g[(b * 64 + c) * N + n0 + np];
            float d = f2g[(b * 64 + c) * N + n0 + np];
            s_f12[i] = pk2(a, d);
            s_f21[i] = pk2(d, a);
        }
        __syncthreads();
        const int m = tid & 63, grp = tid >> 6;  // grp 0..7, 2 points each
        ull bq = pk2(b11[m], b22[m]);
        ull a0 = bq, a1 = bq, r0 = bq, r1v = bq;
        const int np = grp * 2;
        #pragma unroll 8
        for (int c = 0; c < 64; c++) {
            ull wv = s_wp[c * 64 + m];
            a0  = ffma2(s_f12[c * 16 + np],     wv, a0);
            a1  = ffma2(s_f12[c * 16 + np + 1], wv, a1);
            r0  = ffma2(s_f21[c * 16 + np],     wv, r0);
            r1v = ffma2(s_f21[c * 16 + np + 1], wv, r1v);
        }
        float v1, v2;
        int q = (b * N + n0 + np) * 64 + m;
        unpk2(v1, v2, a0);  q1o[q] = v1;      q2o[q] = v2;
        unpk2(v1, v2, a1);  q1o[q + 64] = v1; q2o[q + 64] = v2;
        unpk2(v1, v2, r0);  r1o[q] = v1;      r2o[q] = v2;
        unpk2(v1, v2, r1v); r1o[q + 64] = v1; r2o[q + 64] = v2;
        return;
    }

    // ---- KNN: 2 queries per warp, top-16 list per 16-lane half ----
    if (blockIdx.x >= N / 32) return;
    ulonglong2* s_t0 = (ulonglong2*)smraw;     // 2048: (x-pair, y-pair)
    ulonglong2* s_t1 = s_t0 + (TILE / 2);      // 2048: (z-pair, |p|^2-pair)
    const int dir = blockIdx.z;
    const float* q  = dir ? pc2 : pc1;
    const float* db = dir ? pc1 : pc2;
    int* oi = dir ? i21 : i12;
    const int b = blockIdx.y;
    const int warp = tid >> 5, lane = tid & 31;
    const int nA = blockIdx.x * 32 + warp * 2;
    const int nB = nA + 1;
    const float* qb = q + b * 3 * N;
    const ull m2qAx = dup2(-2.0f * qb[nA]);
    const ull m2qAy = dup2(-2.0f * qb[N + nA]);
    const ull m2qAz = dup2(-2.0f * qb[2 * N + nA]);
    const ull m2qBx = dup2(-2.0f * qb[nB]);
    const ull m2qBy = dup2(-2.0f * qb[N + nB]);
    const ull m2qBz = dup2(-2.0f * qb[2 * N + nB]);
    const float* dbb = db + b * 3 * N;

    float bd = 3.0e38f;   // sorted ascending within each 16-lane half
    int bi = 0;
    float tauA = 3.0e38f, tauB = 3.0e38f;
    const bool halfA = (lane < 16);

    for (int t = 0; t < N; t += TILE) {
        __syncthreads();
        const float2* gx = (const float2*)(dbb + t);
        const float2* gy = (const float2*)(dbb + N + t);
        const float2* gz = (const float2*)(dbb + 2 * N + t);
        for (int i = tid; i < TILE / 2; i += 512) {
            float2 x = gx[i], y = gy[i], z = gz[i];
            float w0 = x.x * x.x + y.x * y.x + z.x * z.x;
            float w1 = x.y * x.y + y.y * y.y + z.y * z.y;
            ulonglong2 A, B;
            A.x = *(const ull*)&x; A.y = *(const ull*)&y;
            B.x = *(const ull*)&z; B.y = pk2(w0, w1);
            s_t0[i] = A; s_t1[i] = B;
        }
        __syncthreads();
        #pragma unroll 4
        for (int p = 0; p < TILE / 2; p += 32) {
            ulonglong2 t0 = s_t0[p + lane];
            ulonglong2 t1 = s_t1[p + lane];
            ull dA = ffma2(t0.x, m2qAx, t1.y);
            dA = ffma2(t0.y, m2qAy, dA);
            dA = ffma2(t1.x, m2qAz, dA);
            ull dB = ffma2(t0.x, m2qBx, t1.y);
            dB = ffma2(t0.y, m2qBy, dB);
            dB = ffma2(t1.x, m2qBz, dB);
            float dA0, dA1, dB0, dB1;
            unpk2(dA0, dA1, dA);
            unpk2(dB0, dB1, dB);
            bool hit = (fminf(dA0, dA1) < tauA) | (fminf(dB0, dB1) < tauB);
            if (__ballot_sync(FULLMASK, hit)) {
                const int base = t + 2 * p;
                unsigned mA0 = __ballot_sync(FULLMASK, dA0 < tauA);
                unsigned mA1 = __ballot_sync(FULLMASK, dA1 < tauA);
                unsigned mB0 = __ballot_sync(FULLMASK, dB0 < tauB);
                unsigned mB1 = __ballot_sync(FULLMASK, dB1 < tauB);
                unsigned mm0 = halfA ? mA0 : mB0;
                unsigned mm1 = halfA ? mA1 : mB1;
                // element-0 candidates
                while (__ballot_sync(FULLMASK, mm0 != 0)) {
                    int src = __ffs(mm0) - 1;        // uniform per half (or -1)
                    float vA = __shfl_sync(FULLMASK, dA0, src & 31);
                    float vB = __shfl_sync(FULLMASK, dB0, src & 31);
                    float dd = halfA ? vA : vB;
                    float up  = __shfl_up_sync(FULLMASK, bd, 1, 16);
                    int   upi = __shfl_up_sync(FULLMASK, bi, 1, 16);
                    if ((lane & 15) == 0) up = -3.0e38f;
                    if (mm0 && bd > dd) {
                        bool tk = up > dd;
                        bd = tk ? up : dd;
                        bi = tk ? upi : base + 2 * src;
                    }
                    mm0 &= mm0 - 1;
                }
                // element-1 candidates
                while (__ballot_sync(FULLMASK, mm1 != 0)) {
                    int src = __ffs(mm1) - 1;
                    float vA = __shfl_sync(FULLMASK, dA1, src & 31);
                    float vB = __shfl_sync(FULLMASK, dB1, src & 31);
                    float dd = halfA ? vA : vB;
                    float up  = __shfl_up_sync(FULLMASK, bd, 1, 16);
                    int   upi = __shfl_up_sync(FULLMASK, bi, 1, 16);
                    if ((lane & 15) == 0) up = -3.0e38f;
                    if (mm1 && bd > dd) {
                        bool tk = up > dd;
                        bd = tk ? up : dd;
                        bi = tk ? upi : base + 2 * src + 1;
                    }
                    mm1 &= mm1 - 1;
                }
                tauA = __shfl_sync(FULLMASK, bd, 15);
                tauB = __shfl_sync(FULLMASK, bd, 31);
            }
        }
    }
    const int nOut = halfA ? nA : nB;
    oi[((b * N) + nOut) * 16 + (lane & 15)] = bi;
}

// ================= fused cross (+ optional final-linear epilogue) =================
// smem float offsets
#define OW1 0
#define OW2 4096
#define OW3 8192
#define OPWT 12288
#define OPB  12480
#define OB1  12544
#define OB2  12608
#define OB3  12672
#define OHP  12736                 // ull region: 8 warps * 512 = 4096 ull
#define OST  (12736 + 4096*2)      // float offset of stash: 8 warps * 256 ull
#define SMEM_FLOATS (12736 + 4096*2 + 2048*2)

template <int NL, int EPI>
__global__ __launch_bounds__(256) void cross_kernel(
    const int* __restrict__ iA, const int* __restrict__ iB,
    const float* __restrict__ xA, const float* __restrict__ xB,
    const float* __restrict__ p1A, const float* __restrict__ p2A,
    const float* __restrict__ p1B, const float* __restrict__ p2B,
    const float* __restrict__ posw, const float* __restrict__ posb,
    const float* __restrict__ w1, const float* __restrict__ b1,
    const float* __restrict__ w2, const float* __restrict__ b2,
    const float* __restrict__ w3A, const float* __restrict__ b3A,
    const float* __restrict__ w3B, const float* __restrict__ b3B,
    float* __restrict__ obnA, float* __restrict__ obnB,
    float* __restrict__ ocnA, float* __restrict__ ocnB)
{
    extern __shared__ float sm[];
    float* s_w1  = sm + OW1;
    float* s_w2  = sm + OW2;
    float* s_w3  = sm + OW3;
    float* s_pwt = sm + OPWT;
    float* s_pb  = sm + OPB;
    float* s_b1  = sm + OB1;
    float* s_b2  = sm + OB2;
    float* s_b3  = sm + OB3;
    ull*   s_hp  = (ull*)(sm + OHP);
    ull*   s_st  = (ull*)(sm + OST);

    const int dir = blockIdx.y;
    const int* idx = dir ? iB : iA;
    const float* xyz1 = dir ? xB : xA;
    const float* xyz2 = dir ? xA : xB;
    const float* p1 = dir ? p1B : p1A;
    const float* p2 = dir ? p2B : p2A;
    const float* w3 = dir ? w3B : w3A;
    const float* b3 = dir ? b3B : b3A;
    float* obn = dir ? obnB : obnA;
    float* ocn = dir ? ocnB : ocnA;

    const int tid = threadIdx.x;
    for (int i = tid; i < 4096; i += 256) {
        int jb = i >> 8, c = (i >> 2) & 63, u = i & 3;
        s_w1[i] = w1[c * 64 + jb * 4 + u];
        if (NL == 2) s_w2[i] = w2[c * 64 + jb * 4 + u];
        if (EPI)     s_w3[i] = w3[c * 64 + jb * 4 + u];
    }
    if (tid < 192) s_pwt[tid] = posw[(tid & 63) * 3 + (tid >> 6)];
    if (tid < 64) {
        s_pb[tid] = posb[tid];
        s_b1[tid] = b1[tid];
        if (NL == 2) s_b2[tid] = b2[tid];
        if (EPI)     s_b3[tid] = b3[tid];
    }
    __syncthreads();

    const int warp = tid >> 5, lane = tid & 31;
    ull* shp = s_hp + warp * 512;
    ull* sst = s_st + warp * 256;
    const int wq0 = (blockIdx.x * 8 + warp) * 8;

    const float pw0a = s_pwt[lane],      pw1a = s_pwt[64 + lane],  pw2a = s_pwt[128 + lane];
    const float pw0b = s_pwt[lane + 32], pw1b = s_pwt[96 + lane],  pw2b = s_pwt[160 + lane];
    const float pba = s_pb[lane], pbb = s_pb[lane + 32];
    const ull bd1a = dup2(s_b1[lane]), bd1b = dup2(s_b1[lane + 32]);
    const ull bd2a = (NL == 2) ? dup2(s_b2[lane]) : 0ull;
    const ull bd2b = (NL == 2) ? dup2(s_b2[lane + 32]) : 0ull;

    float pma = 0.f, pmb = 0.f;

    for (int qi = 0; qi < 8; qi++) {
        const int q = wq0 + qi;
        const int b = q >> 13, n = q & (N - 1);
        const int myidx = idx[q * 16 + (lane & 15)];
        const float p1a = p1[q * 64 + lane];
        const float p1b = p1[q * 64 + 32 + lane];
        const float* x1b = xyz1 + b * 3 * N;
        const float qx = x1b[n], qy = x1b[N + n], qz = x1b[2 * N + n];
        const float* x2b = xyz2 + b * 3 * N;
        const float nx = x2b[myidx], ny = x2b[N + myidx], nz = x2b[2 * N + myidx];

        float pva = 0.f, pvb = 0.f;
        #pragma unroll
        for (int k = 0; k < 16; k++) {
            int j = __shfl_sync(FULLMASK, myidx, k);
            float dx = __shfl_sync(FULLMASK, nx, k) - qx;
            float dy = __shfl_sync(FULLMASK, ny, k) - qy;
            float dz = __shfl_sync(FULLMASK, nz, k) - qz;
            const float* p2r = p2 + ((size_t)((b << 13) + j)) * 64;
            float ga = p2r[lane], gb = p2r[lane + 32];
            float pa = pba + dx * pw0a + dy * pw1a + dz * pw2a;
            float pb = pbb + dx * pw0b + dy * pw1b + dz * pw2b;
            float ha = leaky(ga + p1a + pa);
            float hb = leaky(gb + p1b + pb);
            if (k & 1) {
                shp[(k >> 1) * 64 + lane]      = pk2(pva, ha);
                shp[(k >> 1) * 64 + lane + 32] = pk2(pvb, hb);
            } else { pva = ha; pvb = hb; }
        }
        __syncwarp();

        ull ya[8], yb[8];
        #pragma unroll
        for (int k2 = 0; k2 < 8; k2++) { ya[k2] = bd1a; yb[k2] = bd1b; }
        #pragma unroll
        for (int jb = 0; jb < 16; jb++) {
            float4 wa = *(const float4*)(s_w1 + (jb * 64 + lane) * 4);
            float4 wb = *(const float4*)(s_w1 + (jb * 64 + lane + 32) * 4);
            ull wax = dup2(wa.x), way = dup2(wa.y), waz = dup2(wa.z), waw = dup2(wa.w);
            ull wbx = dup2(wb.x), wby = dup2(wb.y), wbz = dup2(wb.z), wbw = dup2(wb.w);
            #pragma unroll
            for (int k2 = 0; k2 < 8; k2++) {
                ulonglong2 h01 = *(const ulonglong2*)(shp + k2 * 64 + jb * 4);
                ulonglong2 h23 = *(const ulonglong2*)(shp + k2 * 64 + jb * 4 + 2);
                ya[k2] = ffma2(h01.x, wax, ya[k2]);
                yb[k2] = ffma2(h01.x, wbx, yb[k2]);
                ya[k2] = ffma2(h01.y, way, ya[k2]);
                yb[k2] = ffma2(h01.y, wby, yb[k2]);
                ya[k2] = ffma2(h23.x, waz, ya[k2]);
                yb[k2] = ffma2(h23.x, wbz, yb[k2]);
                ya[k2] = ffma2(h23.y, waw, ya[k2]);
                yb[k2] = ffma2(h23.y, wbw, yb[k2]);
            }
        }

        if (NL == 2) {
            __syncwarp();
            #pragma unroll
            for (int k2 = 0; k2 < 8; k2++) {
                shp[k2 * 64 + lane]      = lky2(ya[k2]);
                shp[k2 * 64 + lane + 32] = lky2(yb[k2]);
            }
            __syncwarp();
            #pragma unroll
            for (int k2 = 0; k2 < 8; k2++) { ya[k2] = bd2a; yb[k2] = bd2b; }
            #pragma unroll
            for (int jb = 0; jb < 16; jb++) {
                float4 wa = *(const float4*)(s_w2 + (jb * 64 + lane) * 4);
                float4 wb = *(const float4*)(s_w2 + (jb * 64 + lane + 32) * 4);
                ull wax = dup2(wa.x), way = dup2(wa.y), waz = dup2(wa.z), waw = dup2(wa.w);
                ull wbx = dup2(wb.x), wby = dup2(wb.y), wbz = dup2(wb.z), wbw = dup2(wb.w);
                #pragma unroll
                for (int k2 = 0; k2 < 8; k2++) {
                    ulonglong2 h01 = *(const ulonglong2*)(shp + k2 * 64 + jb * 4);
                    ulonglong2 h23 = *(const ulonglong2*)(shp + k2 * 64 + jb * 4 + 2);
                    ya[k2] = ffma2(h01.x, wax, ya[k2]);
                    yb[k2] = ffma2(h01.x, wbx, yb[k2]);
                    ya[k2] = ffma2(h01.y, way, ya[k2]);
                    yb[k2] = ffma2(h01.y, wby, yb[k2]);
                    ya[k2] = ffma2(h23.x, waz, ya[k2]);
                    yb[k2] = ffma2(h23.x, wbz, yb[k2]);
                    ya[k2] = ffma2(h23.y, waw, ya[k2]);
                    yb[k2] = ffma2(h23.y, wbw, yb[k2]);
                }
            }
        }

        float ma = -3.0e38f, mb = -3.0e38f;
        #pragma unroll
        for (int k2 = 0; k2 < 8; k2++) {
            float u, v;
            unpk2(u, v, ya[k2]); ma = fmaxf(ma, fmaxf(u, v));
            unpk2(u, v, yb[k2]); mb = fmaxf(mb, fmaxf(u, v));
        }
        ma = leaky(ma); mb = leaky(mb);

        if (EPI) {
            if (qi & 1) {
                sst[(qi >> 1) * 64 + lane]      = pk2(pma, ma);
                sst[(qi >> 1) * 64 + 32 + lane] = pk2(pmb, mb);
            } else { pma = ma; pmb = mb; }
        } else {
            // transposed direct write (cross3)
            ocn[((b * 64) + lane) * N + n] = ma;
            ocn[((b * 64) + lane + 32) * N + n] = mb;
        }
        __syncwarp();
    }

    if (EPI) {
        __syncwarp();
        ull za[4], zb[4];
        const ull bd3a = dup2(s_b3[lane]), bd3b = dup2(s_b3[lane + 32]);
        #pragma unroll
        for (int q2 = 0; q2 < 4; q2++) { za[q2] = bd3a; zb[q2] = bd3b; }
        #pragma unroll
        for (int jb = 0; jb < 16; jb++) {
            float4 wa = *(const float4*)(s_w3 + (jb * 64 + lane) * 4);
            float4 wb = *(const float4*)(s_w3 + (jb * 64 + lane + 32) * 4);
            ull wax = dup2(wa.x), way = dup2(wa.y), waz = dup2(wa.z), waw = dup2(wa.w);
            ull wbx = dup2(wb.x), wby = dup2(wb.y), wbz = dup2(wb.z), wbw = dup2(wb.w);
            #pragma unroll
            for (int q2 = 0; q2 < 4; q2++) {
                ulonglong2 h01 = *(const ulonglong2*)(sst + q2 * 64 + jb * 4);
                ulonglong2 h23 = *(const ulonglong2*)(sst + q2 * 64 + jb * 4 + 2);
                za[q2] = ffma2(h01.x, wax, za[q2]);
                zb[q2] = ffma2(h01.x, wbx, zb[q2]);
                za[q2] = ffma2(h01.y, way, za[q2]);
                zb[q2] = ffma2(h01.y, wby, zb[q2]);
                za[q2] = ffma2(h23.x, waz, za[q2]);
                zb[q2] = ffma2(h23.x, wbz, zb[q2]);
                za[q2] = ffma2(h23.y, waw, za[q2]);
                zb[q2] = ffma2(h23.y, wbw, zb[q2]);
            }
        }
        #pragma unroll
        for (int q2 = 0; q2 < 4; q2++) {
            const int q = wq0 + 2 * q2;
            const int b = q >> 13, n = q & (N - 1);
            float lo, hi;
            unpk2(lo, hi, za[q2]);
            obn[q * 64 + lane] = lo;
            obn[(q + 1) * 64 + lane] = hi;
            *(float2*)&ocn[((b * 64) + lane) * N + n] = make_float2(lo, hi);
            unpk2(lo, hi, zb[q2]);
            obn[q * 64 + 32 + lane] = lo;
            obn[(q + 1) * 64 + 32 + lane] = hi;
            *(float2*)&ocn[((b * 64) + lane + 32) * N + n] = make_float2(lo, hi);
        }
    }
}

// ---------------- launch ----------------
extern "C" void kernel_launch(void* const* d_in, const int* in_sizes, int n_in,
                              void* d_out, int out_size)
{
    const float* pc1     = (const float*)d_in[0];
    const float* pc2     = (const float*)d_in[1];
    const float* feat1   = (const float*)d_in[2];
    const float* feat2   = (const float*)d_in[3];
    const float* t11_w   = (const float*)d_in[4];
    const float* t11_b   = (const float*)d_in[5];
    const float* t22_w   = (const float*)d_in[6];
    const float* t22_b   = (const float*)d_in[7];
    const float* pos1_w  = (const float*)d_in[8];
    const float* pos1_b  = (const float*)d_in[9];
    const float* mlp1_w1 = (const float*)d_in[10];
    const float* mlp1_b1 = (const float*)d_in[11];
    const float* mlp1_w2 = (const float*)d_in[12];
    const float* mlp1_b2 = (const float*)d_in[13];
    const float* t1_w    = (const float*)d_in[14];
    const float* t1_b    = (const float*)d_in[15];
    const float* t2_w    = (const float*)d_in[16];
    const float* t2_b    = (const float*)d_in[17];
    const float* pos2_w  = (const float*)d_in[18];
    const float* pos2_b  = (const float*)d_in[19];
    const float* mlp2_w1 = (const float*)d_in[20];
    const float* mlp2_b1 = (const float*)d_in[21];
    float* out = (float*)d_out;

    float *q1, *q2, *r1, *r2, *f1, *f2;
    int *i12, *i21;
    cudaGetSymbolAddress((void**)&q1, g_q1);
    cudaGetSymbolAddress((void**)&q2, g_q2);
    cudaGetSymbolAddress((void**)&r1, g_r1);
    cudaGetSymbolAddress((void**)&r2, g_r2);
    cudaGetSymbolAddress((void**)&f1, g_f1);
    cudaGetSymbolAddress((void**)&f2, g_f2);
    cudaGetSymbolAddress((void**)&i12, g_i12);
    cudaGetSymbolAddress((void**)&i21, g_i21);

    // fused KNN (z=0,1; grid.x<256 active) + transforms (z=2; grid.x<512 active)
    const size_t smem_kt = (size_t)TILE / 2 * 32;   // 64KB
    cudaFuncSetAttribute(knn_transform_kernel, cudaFuncAttributeMaxDynamicSharedMemorySize, (int)smem_kt);
    knn_transform_kernel<<<dim3(N / 16, BB, 3), 512, smem_kt>>>(
        pc1, pc2, i12, i21,
        feat1, feat2, t11_w, t11_b, t22_w, t22_b,
        q1, q2, r1, r2);

    const size_t smem = (size_t)SMEM_FLOATS * sizeof(float);
    cudaFuncSetAttribute(cross_kernel<2,1>, cudaFuncAttributeMaxDynamicSharedMemorySize, (int)smem);
    cudaFuncSetAttribute(cross_kernel<1,0>, cudaFuncAttributeMaxDynamicSharedMemorySize, (int)smem);

    // cross 1 & 2 fused (grid.y = direction) with final-linear epilogue
    cross_kernel<2,1><<<dim3(BB * N / 64, 2), 256, smem>>>(
        i12, i21, pc1, pc2,
        q1, q2, r1, r2,
        pos1_w, pos1_b, mlp1_w1, mlp1_b1, mlp1_w2, mlp1_b2,
        t1_w, t1_b, t2_w, t2_b,
        f1, f2, out, out + (size_t)BB * 64 * N);

    // cross 3 (1 mlp layer), transposed direct write to output region 2
    cross_kernel<1,0><<<dim3(BB * N / 64, 1), 256, smem>>>(
        i12, i12, pc1, pc2,
        f1, f2, f1, f2,
        pos2_w, pos2_b, mlp2_w1, mlp2_b1, mlp2_w1, mlp2_b1,
        mlp2_w1, mlp2_b1, mlp2_w1, mlp2_b1,
        out + (size_t)2 * BB * 64 * N, out + (size_t)2 * BB * 64 * N,
        out + (size_t)2 * BB * 64 * N, out + (size_t)2 * BB * 64 * N);
}